// round 1
// baseline (speedup 1.0000x reference)
#include <cuda_runtime.h>
#include <math.h>

#define N_NODES 100000
#define N_EDGES 1600000
#define F_IN    256
#define F_HID   128
#define F_OUT   40
#define NSCAN_BLK 98            // ceil(100000/1024)

// ---------------- device scratch (static globals: allowed) ----------------
__device__ int   g_is64;
__device__ int   g_deg[N_NODES];
__device__ float g_dinv[N_NODES];
__device__ int   g_rowptr[N_NODES + 1];
__device__ int   g_cursor[N_NODES];
__device__ int   g_src[N_EDGES];
__device__ int   g_dst[N_EDGES];
__device__ int   g_ssrc[N_EDGES];       // src ids sorted by dst
__device__ int   g_bsum[NSCAN_BLK];
__device__ float g_H1[(size_t)N_NODES * F_HID];   // x @ W1
__device__ float g_h [(size_t)N_NODES * F_HID];   // relu(agg1 + b1)
__device__ float g_H2[(size_t)N_NODES * F_OUT];   // h @ W2
__device__ float g_W2p[F_HID * 64];               // W2 padded to 64 cols

// ---------------- dtype detection -----------------------------------------
// int64 edge_index (little endian, values < 2^31) has all odd 32-bit words 0.
// For int32 random ids in [0,1e5), P(512 odd words all zero) ~ 0.
__global__ void k_detect(const unsigned* __restrict__ w) {
    __shared__ int any;
    if (threadIdx.x == 0) any = 0;
    __syncthreads();
    for (int j = threadIdx.x; j < 512; j += blockDim.x)
        if (w[2 * j + 1] != 0u) atomicOr(&any, 1);
    __syncthreads();
    if (threadIdx.x == 0) g_is64 = (any == 0);
}

__global__ void k_init_deg() {
    int i = blockIdx.x * blockDim.x + threadIdx.x;
    if (i < N_NODES) g_deg[i] = 1;   // self loop
}

// canonicalize edges to int32 + degree histogram
__global__ void k_convert(const void* __restrict__ ei) {
    int e = blockIdx.x * blockDim.x + threadIdx.x;
    if (e >= N_EDGES) return;
    int s, d;
    if (g_is64) {
        const long long* p = (const long long*)ei;
        s = (int)p[e];
        d = (int)p[N_EDGES + e];
    } else {
        const int* p = (const int*)ei;
        s = p[e];
        d = p[N_EDGES + e];
    }
    g_src[e] = s;
    g_dst[e] = d;
    atomicAdd(&g_deg[d], 1);
}

__global__ void k_dinv() {
    int i = blockIdx.x * blockDim.x + threadIdx.x;
    if (i < N_NODES) g_dinv[i] = rsqrtf((float)g_deg[i]);
}

// ---------------- CSR build: 2-level exclusive scan of (deg-1) -------------
__global__ void k_scan1() {
    __shared__ int sh[1024];
    int tid = threadIdx.x;
    int i = blockIdx.x * 1024 + tid;
    int v = (i < N_NODES) ? (g_deg[i] - 1) : 0;
    sh[tid] = v;
    __syncthreads();
    for (int off = 1; off < 1024; off <<= 1) {
        int t = (tid >= off) ? sh[tid - off] : 0;
        __syncthreads();
        sh[tid] += t;
        __syncthreads();
    }
    if (i < N_NODES) g_rowptr[i] = sh[tid] - v;   // exclusive
    if (tid == 1023) g_bsum[blockIdx.x] = sh[1023];
}

__global__ void k_scan2() {
    __shared__ int sh[128];
    int tid = threadIdx.x;
    int v = (tid < NSCAN_BLK) ? g_bsum[tid] : 0;
    sh[tid] = v;
    __syncthreads();
    for (int off = 1; off < 128; off <<= 1) {
        int t = (tid >= off) ? sh[tid - off] : 0;
        __syncthreads();
        sh[tid] += t;
        __syncthreads();
    }
    if (tid < NSCAN_BLK) g_bsum[tid] = sh[tid] - v;
}

__global__ void k_scan3() {
    int i = blockIdx.x * blockDim.x + threadIdx.x;
    if (i < N_NODES) {
        int r = g_rowptr[i] + g_bsum[i >> 10];
        g_rowptr[i] = r;
        g_cursor[i] = r;
    } else if (i == N_NODES) {
        g_rowptr[N_NODES] = N_EDGES;
    }
}

__global__ void k_scatter() {
    int e = blockIdx.x * blockDim.x + threadIdx.x;
    if (e >= N_EDGES) return;
    int d = g_dst[e];
    int p = atomicAdd(&g_cursor[d], 1);
    g_ssrc[p] = g_src[e];
}

// ---------------- SGEMM: 128x64 tile, 8x4 per thread, BK=8 -----------------
__global__ __launch_bounds__(256) void k_sgemm(
    const float* __restrict__ A, int lda,
    const float* __restrict__ B, int ldb,
    float* __restrict__ C, int ldc,
    int M, int Nact, int K)
{
    __shared__ float As[8][132];
    __shared__ float Bs[8][64];
    int tid = threadIdx.x;
    int tx = tid & 15, ty = tid >> 4;
    int m0 = blockIdx.x * 128;
    int n0 = blockIdx.y * 64;

    float acc[8][4];
#pragma unroll
    for (int i = 0; i < 8; i++)
#pragma unroll
        for (int j = 0; j < 4; j++) acc[i][j] = 0.f;

    int am = tid >> 1;              // 0..127
    int ak = (tid & 1) * 4;         // 0 or 4
    int arow = m0 + am;
    if (arow >= M) arow = M - 1;    // clamp (stores guarded)
    int bk = tid >> 4;              // used for tid<128: 0..7
    int bn = (tid & 15) * 4;

    for (int k0 = 0; k0 < K; k0 += 8) {
        float4 av = *(const float4*)(A + (size_t)arow * lda + k0 + ak);
        As[ak + 0][am] = av.x;
        As[ak + 1][am] = av.y;
        As[ak + 2][am] = av.z;
        As[ak + 3][am] = av.w;
        if (tid < 128) {
            float4 bv = *(const float4*)(B + (size_t)(k0 + bk) * ldb + n0 + bn);
            *(float4*)&Bs[bk][bn] = bv;
        }
        __syncthreads();
#pragma unroll
        for (int k = 0; k < 8; ++k) {
            float4 a0 = *(const float4*)&As[k][ty * 8];
            float4 a1 = *(const float4*)&As[k][ty * 8 + 4];
            float4 bv = *(const float4*)&Bs[k][tx * 4];
            float a[8] = {a0.x, a0.y, a0.z, a0.w, a1.x, a1.y, a1.z, a1.w};
            float b[4] = {bv.x, bv.y, bv.z, bv.w};
#pragma unroll
            for (int i = 0; i < 8; i++)
#pragma unroll
                for (int j = 0; j < 4; j++) acc[i][j] += a[i] * b[j];
        }
        __syncthreads();
    }
#pragma unroll
    for (int i = 0; i < 8; i++) {
        int row = m0 + ty * 8 + i;
        if (row < M) {
#pragma unroll
            for (int j = 0; j < 4; j++) {
                int col = n0 + tx * 4 + j;
                if (col < Nact) C[(size_t)row * ldc + col] = acc[i][j];
            }
        }
    }
}

__global__ void k_pad_w2(const float* __restrict__ W2) {
    int idx = blockIdx.x * blockDim.x + threadIdx.x;
    if (idx >= F_HID * 64) return;
    int k = idx >> 6, j = idx & 63;
    g_W2p[idx] = (j < F_OUT) ? W2[k * F_OUT + j] : 0.f;
}

// ---------------- layer-1 aggregation: warp per node (128 feats) ----------
__global__ __launch_bounds__(256) void k_agg1(const float* __restrict__ b1) {
    int node = (blockIdx.x * blockDim.x + threadIdx.x) >> 5;
    if (node >= N_NODES) return;
    int lane = threadIdx.x & 31;
    float di = g_dinv[node];
    float wself = di * di;

    const float4* srow = (const float4*)(g_H1 + (size_t)node * F_HID);
    float4 v = srow[lane];
    float4 acc;
    acc.x = wself * v.x; acc.y = wself * v.y;
    acc.z = wself * v.z; acc.w = wself * v.w;

    int beg = g_rowptr[node], end = g_rowptr[node + 1];
    for (int p0 = beg; p0 < end; p0 += 32) {
        int myp = p0 + lane;
        int s = (myp < end) ? g_ssrc[myp] : 0;
        float ws = (myp < end) ? g_dinv[s] * di : 0.f;
        int cnt = min(32, end - p0);
        for (int j = 0; j < cnt; ++j) {
            int   sj = __shfl_sync(0xffffffffu, s, j);
            float wj = __shfl_sync(0xffffffffu, ws, j);
            float4 u = ((const float4*)(g_H1 + (size_t)sj * F_HID))[lane];
            acc.x += wj * u.x; acc.y += wj * u.y;
            acc.z += wj * u.z; acc.w += wj * u.w;
        }
    }
    float4 bb = ((const float4*)b1)[lane];
    acc.x = fmaxf(acc.x + bb.x, 0.f);
    acc.y = fmaxf(acc.y + bb.y, 0.f);
    acc.z = fmaxf(acc.z + bb.z, 0.f);
    acc.w = fmaxf(acc.w + bb.w, 0.f);
    ((float4*)(g_h + (size_t)node * F_HID))[lane] = acc;
}

// ---------- layer-2 aggregation + bias + log_softmax: warp per node -------
__global__ __launch_bounds__(256) void k_agg2(const float* __restrict__ b2,
                                              float* __restrict__ out) {
    int node = (blockIdx.x * blockDim.x + threadIdx.x) >> 5;
    if (node >= N_NODES) return;
    int lane = threadIdx.x & 31;
    float di = g_dinv[node];
    float wself = di * di;

    const float* srow = g_H2 + (size_t)node * F_OUT;
    float acc0 = wself * srow[lane];
    float acc1 = (lane < 8) ? wself * srow[32 + lane] : 0.f;

    int beg = g_rowptr[node], end = g_rowptr[node + 1];
    for (int p0 = beg; p0 < end; p0 += 32) {
        int myp = p0 + lane;
        int s = (myp < end) ? g_ssrc[myp] : 0;
        float ws = (myp < end) ? g_dinv[s] * di : 0.f;
        int cnt = min(32, end - p0);
        for (int j = 0; j < cnt; ++j) {
            int   sj = __shfl_sync(0xffffffffu, s, j);
            float wj = __shfl_sync(0xffffffffu, ws, j);
            const float* r = g_H2 + (size_t)sj * F_OUT;
            acc0 += wj * r[lane];
            if (lane < 8) acc1 += wj * r[32 + lane];
        }
    }
    acc0 += b2[lane];
    if (lane < 8) acc1 += b2[32 + lane];

    // warp log_softmax over 40 values
    float m = acc0;
    if (lane < 8) m = fmaxf(m, acc1);
#pragma unroll
    for (int o = 16; o; o >>= 1) m = fmaxf(m, __shfl_xor_sync(0xffffffffu, m, o));
    float e = expf(acc0 - m) + ((lane < 8) ? expf(acc1 - m) : 0.f);
#pragma unroll
    for (int o = 16; o; o >>= 1) e += __shfl_xor_sync(0xffffffffu, e, o);
    float lse = m + logf(e);

    float* orow = out + (size_t)node * F_OUT;
    orow[lane] = acc0 - lse;
    if (lane < 8) orow[32 + lane] = acc1 - lse;
}

// ---------------- host launcher --------------------------------------------
extern "C" void kernel_launch(void* const* d_in, const int* in_sizes, int n_in,
                              void* d_out, int out_size) {
    const float* x  = (const float*)d_in[0];
    const void*  ei = d_in[1];
    const float* W1 = (const float*)d_in[2];
    const float* b1 = (const float*)d_in[3];
    const float* W2 = (const float*)d_in[4];
    const float* b2 = (const float*)d_in[5];
    float* out = (float*)d_out;

    float *dH1, *dh, *dH2, *dW2p;
    cudaGetSymbolAddress((void**)&dH1,  g_H1);
    cudaGetSymbolAddress((void**)&dh,   g_h);
    cudaGetSymbolAddress((void**)&dH2,  g_H2);
    cudaGetSymbolAddress((void**)&dW2p, g_W2p);

    const int TB = 256;
    int nblkN = (N_NODES + TB - 1) / TB;       // 391
    int nblkE = (N_EDGES + TB - 1) / TB;       // 6250
    int aggBlk = (N_NODES * 32) / TB;          // 12500

    // graph preprocessing
    k_detect<<<1, 256>>>((const unsigned*)ei);
    k_init_deg<<<nblkN, TB>>>();
    k_convert<<<nblkE, TB>>>(ei);
    k_dinv<<<nblkN, TB>>>();
    k_scan1<<<NSCAN_BLK, 1024>>>();
    k_scan2<<<1, 128>>>();
    k_scan3<<<(N_NODES + 1 + TB - 1) / TB, TB>>>();
    k_scatter<<<nblkE, TB>>>();

    // layer 1: H1 = x @ W1 ; h = relu(agg(H1) + b1)
    dim3 g1((N_NODES + 127) / 128, (F_HID + 63) / 64);
    k_sgemm<<<g1, 256>>>(x, F_IN, W1, F_HID, dH1, F_HID, N_NODES, F_HID, F_IN);
    k_agg1<<<aggBlk, TB>>>(b1);

    // layer 2: H2 = h @ W2 ; out = log_softmax(agg(H2) + b2)
    k_pad_w2<<<(F_HID * 64 + TB - 1) / TB, TB>>>(W2);
    dim3 g2((N_NODES + 127) / 128, 1);
    k_sgemm<<<g2, 256>>>(dh, F_HID, dW2p, 64, dH2, F_OUT, N_NODES, F_OUT, F_HID);
    k_agg2<<<aggBlk, TB>>>(b2, out);
}

// round 3
// speedup vs baseline: 1.3048x; 1.3048x over previous
#include <cuda_runtime.h>
#include <cuda_bf16.h>
#include <math.h>
#include <stdint.h>

#define N_NODES 100000
#define N_EDGES 1600000
#define F_IN    256
#define F_HID   128
#define F_OUT   40
#define NSCAN_BLK 98            // ceil(100000/1024)

// ---------------- device scratch (static globals: allowed) ----------------
__device__ int   g_is64;
__device__ int   g_deg[N_NODES];
__device__ float g_dinv[N_NODES];
__device__ int   g_rowptr[N_NODES + 1];
__device__ int   g_cursor[N_NODES];
__device__ int   g_src[N_EDGES];
__device__ int   g_dst[N_EDGES];
__device__ int   g_ssrc[N_EDGES];       // src ids sorted by dst
__device__ int   g_bsum[NSCAN_BLK];
__device__ float g_H1[(size_t)N_NODES * F_HID];   // x @ W1
__device__ float g_h [(size_t)N_NODES * F_HID];   // relu(agg1 + b1)
__device__ float g_H2[(size_t)N_NODES * F_OUT];   // h @ W2
// W^T baked as N-major bf16 hi/lo: [N][K]
__device__ __align__(16) __nv_bfloat16 g_B1hi[128 * 256];
__device__ __align__(16) __nv_bfloat16 g_B1lo[128 * 256];
__device__ __align__(16) __nv_bfloat16 g_B2hi[64 * 128];
__device__ __align__(16) __nv_bfloat16 g_B2lo[64 * 128];

// ======================= mma.sync helpers (sm_80+ baseline PTX) ============
__device__ __forceinline__ uint32_t smem_u32(const void* p) {
    uint32_t a;
    asm("{ .reg .u64 t; cvta.to.shared.u64 t, %1; cvt.u32.u64 %0, t; }"
        : "=r"(a) : "l"(p));
    return a;
}

__device__ __forceinline__ void ldsm_x4(uint32_t* r, uint32_t addr) {
    asm volatile("ldmatrix.sync.aligned.m8n8.x4.shared.b16 {%0,%1,%2,%3}, [%4];"
                 : "=r"(r[0]), "=r"(r[1]), "=r"(r[2]), "=r"(r[3]) : "r"(addr));
}

__device__ __forceinline__ void mma_bf16(float* c, const uint32_t* a, const uint32_t* b) {
    asm volatile(
        "mma.sync.aligned.m16n8k16.row.col.f32.bf16.bf16.f32 "
        "{%0,%1,%2,%3}, {%4,%5,%6,%7}, {%8,%9}, {%0,%1,%2,%3};"
        : "+f"(c[0]), "+f"(c[1]), "+f"(c[2]), "+f"(c[3])
        : "r"(a[0]), "r"(a[1]), "r"(a[2]), "r"(a[3]), "r"(b[0]), "r"(b[1]));
}

// =================== tensor-core GEMM via mma.sync, bf16 split =============
// C[M, NOUT] = A[M, KDIM](fp32) @ W, with W^T prebaked N-major bf16 hi/lo.
// CTA tile 128 x NDIM, 8 warps (4 x 2), warp tile 32 x (NDIM/2), K-chunk 64.
// SMEM rows padded to 72 bf16 (144B) for conflict-free ldmatrix.
template <int KDIM, int NDIM, int LDC, int NOUT>
__global__ __launch_bounds__(256, 1) void k_mma_gemm(
    const float* __restrict__ A, int M,
    const __nv_bfloat16* __restrict__ Bhi,
    const __nv_bfloat16* __restrict__ Blo,
    float* __restrict__ C)
{
    constexpr int PAD = 72;                 // bf16 per smem row (144 B)
    constexpr int NJT = (NDIM / 2) / 8;     // 8x8-col mma tiles per warp (8 or 4)
    constexpr int A_HI = 0;
    constexpr int A_LO = 128 * PAD;
    constexpr int B_HI = 2 * 128 * PAD;
    constexpr int B_LO = B_HI + NDIM * PAD;

    extern __shared__ __nv_bfloat16 sm[];
    const uint32_t sb = smem_u32(sm);

    const int tid  = threadIdx.x;
    const int wid  = tid >> 5;
    const int lane = tid & 31;
    const int wm = wid & 3;                 // warp row    (0..3)
    const int wn = wid >> 2;                // warp column (0..1)
    const int m_warp = wm * 32;
    const int n_warp = wn * (NDIM / 2);
    const int m0 = blockIdx.x * 128;

    float acc[2][NJT][4];
#pragma unroll
    for (int i = 0; i < 2; i++)
#pragma unroll
        for (int j = 0; j < NJT; j++)
#pragma unroll
            for (int q = 0; q < 4; q++) acc[i][j][q] = 0.f;

    // per-lane ldmatrix offsets (element units)
    const int a_off = (m_warp + (lane & 15)) * PAD + ((lane >> 4) << 3);
    const int b_off = (n_warp + (lane & 7) + ((lane >> 4) << 3)) * PAD
                    + (((lane >> 3) & 1) << 3);

    for (int k0 = 0; k0 < KDIM; k0 += 64) {
        __syncthreads();
        // ---- fill A tile: 128 x 64 fp32 -> bf16 hi/lo ----
        {
            const int iters = 128 * 16 / 256;   // 8
#pragma unroll
            for (int t = 0; t < iters; t++) {
                int i = tid + t * 256;
                int m = i >> 4, q = i & 15;
                int rowg = m0 + m; if (rowg >= M) rowg = M - 1;
                float4 v = *(const float4*)(A + (size_t)rowg * KDIM + k0 + q * 4);
                __nv_bfloat16 h[4], l[4];
                float vv[4] = {v.x, v.y, v.z, v.w};
#pragma unroll
                for (int e = 0; e < 4; e++) {
                    h[e] = __float2bfloat16(vv[e]);
                    l[e] = __float2bfloat16(vv[e] - __bfloat162float(h[e]));
                }
                uint32_t hp0 = ((uint32_t)__bfloat16_as_ushort(h[1]) << 16) | __bfloat16_as_ushort(h[0]);
                uint32_t hp1 = ((uint32_t)__bfloat16_as_ushort(h[3]) << 16) | __bfloat16_as_ushort(h[2]);
                uint32_t lp0 = ((uint32_t)__bfloat16_as_ushort(l[1]) << 16) | __bfloat16_as_ushort(l[0]);
                uint32_t lp1 = ((uint32_t)__bfloat16_as_ushort(l[3]) << 16) | __bfloat16_as_ushort(l[2]);
                uint2* dh = (uint2*)(sm + A_HI + m * PAD + q * 4);
                uint2* dl = (uint2*)(sm + A_LO + m * PAD + q * 4);
                *dh = make_uint2(hp0, hp1);
                *dl = make_uint2(lp0, lp1);
            }
        }
        // ---- fill B tile: NDIM x 64 bf16 hi+lo (prebaked, linear copy) ----
        {
            const int per_img = NDIM * 8;       // uint4 per image
            const int iters = 2 * per_img / 256;
#pragma unroll
            for (int t = 0; t < iters; t++) {
                int i = tid + t * 256;
                int img = i >= per_img;
                int ii = i - img * per_img;
                int r = ii >> 3, q = ii & 7;
                const __nv_bfloat16* src = img ? Blo : Bhi;
                uint4 v = *(const uint4*)(src + (size_t)r * KDIM + k0 + q * 8);
                *(uint4*)(sm + (img ? B_LO : B_HI) + r * PAD + q * 8) = v;
            }
        }
        __syncthreads();

        // ---- 4 k16 steps x 3 split passes ----
#pragma unroll
        for (int kk = 0; kk < 64; kk += 16) {
            uint32_t ah[2][4], al[2][4];
#pragma unroll
            for (int i = 0; i < 2; i++) {
                uint32_t base = (uint32_t)((a_off + i * 16 * PAD + kk) * 2);
                ldsm_x4(ah[i], sb + A_HI * 2 + base);
                ldsm_x4(al[i], sb + A_LO * 2 + base);
            }
            uint32_t bh[NJT][2], bl[NJT][2];
#pragma unroll
            for (int jj = 0; jj < NJT / 2; jj++) {
                uint32_t base = (uint32_t)((b_off + jj * 16 * PAD + kk) * 2);
                uint32_t r[4];
                ldsm_x4(r, sb + B_HI * 2 + base);
                bh[2*jj][0] = r[0]; bh[2*jj][1] = r[1];
                bh[2*jj+1][0] = r[2]; bh[2*jj+1][1] = r[3];
                ldsm_x4(r, sb + B_LO * 2 + base);
                bl[2*jj][0] = r[0]; bl[2*jj][1] = r[1];
                bl[2*jj+1][0] = r[2]; bl[2*jj+1][1] = r[3];
            }
#pragma unroll
            for (int i = 0; i < 2; i++)
#pragma unroll
                for (int j = 0; j < NJT; j++) {
                    mma_bf16(acc[i][j], ah[i], bh[j]);
                    mma_bf16(acc[i][j], ah[i], bl[j]);
                    mma_bf16(acc[i][j], al[i], bh[j]);
                }
        }
    }

    // ---- epilogue: fragment-layout direct stores ----
#pragma unroll
    for (int i = 0; i < 2; i++) {
        int r0 = m0 + m_warp + i * 16 + (lane >> 2);
#pragma unroll
        for (int j = 0; j < NJT; j++) {
            int col = n_warp + j * 8 + (lane & 3) * 2;
            if (col < NOUT) {
                if (r0 < M) {
                    C[(size_t)r0 * LDC + col]     = acc[i][j][0];
                    C[(size_t)r0 * LDC + col + 1] = acc[i][j][1];
                }
                if (r0 + 8 < M) {
                    C[(size_t)(r0 + 8) * LDC + col]     = acc[i][j][2];
                    C[(size_t)(r0 + 8) * LDC + col + 1] = acc[i][j][3];
                }
            }
        }
    }
}

// bake W^T (N-major) hi/lo bf16
__global__ void k_prep_b(const float* __restrict__ W, int K, int N, int nact,
                         __nv_bfloat16* __restrict__ hi,
                         __nv_bfloat16* __restrict__ lo) {
    int idx = blockIdx.x * blockDim.x + threadIdx.x;
    if (idx >= N * K) return;
    int n = idx / K, k = idx % K;
    float v = (n < nact) ? W[(size_t)k * nact + n] : 0.f;
    __nv_bfloat16 h = __float2bfloat16(v);
    hi[idx] = h;
    lo[idx] = __float2bfloat16(v - __bfloat162float(h));
}

// ---------------- dtype detection -----------------------------------------
__global__ void k_detect(const unsigned* __restrict__ w) {
    __shared__ int any;
    if (threadIdx.x == 0) any = 0;
    __syncthreads();
    for (int j = threadIdx.x; j < 512; j += blockDim.x)
        if (w[2 * j + 1] != 0u) atomicOr(&any, 1);
    __syncthreads();
    if (threadIdx.x == 0) g_is64 = (any == 0);
}

__global__ void k_init_deg() {
    int i = blockIdx.x * blockDim.x + threadIdx.x;
    if (i < N_NODES) g_deg[i] = 1;   // self loop
}

__global__ void k_convert(const void* __restrict__ ei) {
    int e = blockIdx.x * blockDim.x + threadIdx.x;
    if (e >= N_EDGES) return;
    int s, d;
    if (g_is64) {
        const long long* p = (const long long*)ei;
        s = (int)p[e];
        d = (int)p[N_EDGES + e];
    } else {
        const int* p = (const int*)ei;
        s = p[e];
        d = p[N_EDGES + e];
    }
    g_src[e] = s;
    g_dst[e] = d;
    atomicAdd(&g_deg[d], 1);
}

__global__ void k_dinv() {
    int i = blockIdx.x * blockDim.x + threadIdx.x;
    if (i < N_NODES) g_dinv[i] = rsqrtf((float)g_deg[i]);
}

// ---------------- CSR build: 2-level exclusive scan of (deg-1) -------------
__global__ void k_scan1() {
    __shared__ int sh[1024];
    int tid = threadIdx.x;
    int i = blockIdx.x * 1024 + tid;
    int v = (i < N_NODES) ? (g_deg[i] - 1) : 0;
    sh[tid] = v;
    __syncthreads();
    for (int off = 1; off < 1024; off <<= 1) {
        int t = (tid >= off) ? sh[tid - off] : 0;
        __syncthreads();
        sh[tid] += t;
        __syncthreads();
    }
    if (i < N_NODES) g_rowptr[i] = sh[tid] - v;   // exclusive
    if (tid == 1023) g_bsum[blockIdx.x] = sh[1023];
}

__global__ void k_scan2() {
    __shared__ int sh[128];
    int tid = threadIdx.x;
    int v = (tid < NSCAN_BLK) ? g_bsum[tid] : 0;
    sh[tid] = v;
    __syncthreads();
    for (int off = 1; off < 128; off <<= 1) {
        int t = (tid >= off) ? sh[tid - off] : 0;
        __syncthreads();
        sh[tid] += t;
        __syncthreads();
    }
    if (tid < NSCAN_BLK) g_bsum[tid] = sh[tid] - v;
}

__global__ void k_scan3() {
    int i = blockIdx.x * blockDim.x + threadIdx.x;
    if (i < N_NODES) {
        int r = g_rowptr[i] + g_bsum[i >> 10];
        g_rowptr[i] = r;
        g_cursor[i] = r;
    } else if (i == N_NODES) {
        g_rowptr[N_NODES] = N_EDGES;
    }
}

__global__ void k_scatter() {
    int e = blockIdx.x * blockDim.x + threadIdx.x;
    if (e >= N_EDGES) return;
    int d = g_dst[e];
    int p = atomicAdd(&g_cursor[d], 1);
    g_ssrc[p] = g_src[e];
}

// ---------------- layer-1 aggregation: warp per node (128 feats) ----------
__global__ __launch_bounds__(256) void k_agg1(const float* __restrict__ b1) {
    int node = (blockIdx.x * blockDim.x + threadIdx.x) >> 5;
    if (node >= N_NODES) return;
    int lane = threadIdx.x & 31;
    float di = g_dinv[node];
    float wself = di * di;

    const float4* srow = (const float4*)(g_H1 + (size_t)node * F_HID);
    float4 v = srow[lane];
    float4 acc;
    acc.x = wself * v.x; acc.y = wself * v.y;
    acc.z = wself * v.z; acc.w = wself * v.w;

    int beg = g_rowptr[node], end = g_rowptr[node + 1];
    for (int p0 = beg; p0 < end; p0 += 32) {
        int myp = p0 + lane;
        int s = (myp < end) ? g_ssrc[myp] : 0;
        float ws = (myp < end) ? g_dinv[s] * di : 0.f;
        int cnt = min(32, end - p0);
        for (int j = 0; j < cnt; ++j) {
            int   sj = __shfl_sync(0xffffffffu, s, j);
            float wj = __shfl_sync(0xffffffffu, ws, j);
            float4 u = ((const float4*)(g_H1 + (size_t)sj * F_HID))[lane];
            acc.x += wj * u.x; acc.y += wj * u.y;
            acc.z += wj * u.z; acc.w += wj * u.w;
        }
    }
    float4 bb = ((const float4*)b1)[lane];
    acc.x = fmaxf(acc.x + bb.x, 0.f);
    acc.y = fmaxf(acc.y + bb.y, 0.f);
    acc.z = fmaxf(acc.z + bb.z, 0.f);
    acc.w = fmaxf(acc.w + bb.w, 0.f);
    ((float4*)(g_h + (size_t)node * F_HID))[lane] = acc;
}

// ---------- layer-2 aggregation + bias + log_softmax: warp per node -------
__global__ __launch_bounds__(256) void k_agg2(const float* __restrict__ b2,
                                              float* __restrict__ out) {
    int node = (blockIdx.x * blockDim.x + threadIdx.x) >> 5;
    if (node >= N_NODES) return;
    int lane = threadIdx.x & 31;
    float di = g_dinv[node];
    float wself = di * di;

    const float* srow = g_H2 + (size_t)node * F_OUT;
    float acc0 = wself * srow[lane];
    float acc1 = (lane < 8) ? wself * srow[32 + lane] : 0.f;

    int beg = g_rowptr[node], end = g_rowptr[node + 1];
    for (int p0 = beg; p0 < end; p0 += 32) {
        int myp = p0 + lane;
        int s = (myp < end) ? g_ssrc[myp] : 0;
        float ws = (myp < end) ? g_dinv[s] * di : 0.f;
        int cnt = min(32, end - p0);
        for (int j = 0; j < cnt; ++j) {
            int   sj = __shfl_sync(0xffffffffu, s, j);
            float wj = __shfl_sync(0xffffffffu, ws, j);
            const float* r = g_H2 + (size_t)sj * F_OUT;
            acc0 += wj * r[lane];
            if (lane < 8) acc1 += wj * r[32 + lane];
        }
    }
    acc0 += b2[lane];
    if (lane < 8) acc1 += b2[32 + lane];

    float m = acc0;
    if (lane < 8) m = fmaxf(m, acc1);
#pragma unroll
    for (int o = 16; o; o >>= 1) m = fmaxf(m, __shfl_xor_sync(0xffffffffu, m, o));
    float e = expf(acc0 - m) + ((lane < 8) ? expf(acc1 - m) : 0.f);
#pragma unroll
    for (int o = 16; o; o >>= 1) e += __shfl_xor_sync(0xffffffffu, e, o);
    float lse = m + logf(e);

    float* orow = out + (size_t)node * F_OUT;
    orow[lane] = acc0 - lse;
    if (lane < 8) orow[32 + lane] = acc1 - lse;
}

// ---------------- host launcher --------------------------------------------
extern "C" void kernel_launch(void* const* d_in, const int* in_sizes, int n_in,
                              void* d_out, int out_size) {
    const float* x  = (const float*)d_in[0];
    const void*  ei = d_in[1];
    const float* W1 = (const float*)d_in[2];
    const float* b1 = (const float*)d_in[3];
    const float* W2 = (const float*)d_in[4];
    const float* b2 = (const float*)d_in[5];
    float* out = (float*)d_out;

    float *dH1, *dh, *dH2;
    __nv_bfloat16 *dB1hi, *dB1lo, *dB2hi, *dB2lo;
    cudaGetSymbolAddress((void**)&dH1,   g_H1);
    cudaGetSymbolAddress((void**)&dh,    g_h);
    cudaGetSymbolAddress((void**)&dH2,   g_H2);
    cudaGetSymbolAddress((void**)&dB1hi, g_B1hi);
    cudaGetSymbolAddress((void**)&dB1lo, g_B1lo);
    cudaGetSymbolAddress((void**)&dB2hi, g_B2hi);
    cudaGetSymbolAddress((void**)&dB2lo, g_B2lo);

    // smem: (2*128 + 2*NDIM) rows * 72 bf16 * 2B
    const int SMEM1 = (2 * 128 + 2 * 128) * 72 * 2;   // 73728
    const int SMEM2 = (2 * 128 + 2 * 64) * 72 * 2;    // 55296
    static bool attr_done = false;
    if (!attr_done) {
        cudaFuncSetAttribute(k_mma_gemm<256, 128, 128, 128>,
                             cudaFuncAttributeMaxDynamicSharedMemorySize, SMEM1);
        cudaFuncSetAttribute(k_mma_gemm<128, 64, 40, 40>,
                             cudaFuncAttributeMaxDynamicSharedMemorySize, SMEM2);
        attr_done = true;
    }

    const int TB = 256;
    int nblkN = (N_NODES + TB - 1) / TB;
    int nblkE = (N_EDGES + TB - 1) / TB;
    int aggBlk = (N_NODES * 32) / TB;
    int gemmBlk = (N_NODES + 127) / 128;          // 782

    // graph preprocessing + weight baking
    k_detect<<<1, 256>>>((const unsigned*)ei);
    k_init_deg<<<nblkN, TB>>>();
    k_convert<<<nblkE, TB>>>(ei);
    k_dinv<<<nblkN, TB>>>();
    k_scan1<<<NSCAN_BLK, 1024>>>();
    k_scan2<<<1, 128>>>();
    k_scan3<<<(N_NODES + 1 + TB - 1) / TB, TB>>>();
    k_scatter<<<nblkE, TB>>>();
    k_prep_b<<<(128 * 256 + TB - 1) / TB, TB>>>(W1, 256, 128, 128, dB1hi, dB1lo);
    k_prep_b<<<(64 * 128 + TB - 1) / TB, TB>>>(W2, 128, 64, 40, dB2hi, dB2lo);

    // layer 1: H1 = x @ W1 (HMMA) ; h = relu(agg(H1) + b1)
    k_mma_gemm<256, 128, 128, 128><<<gemmBlk, 256, SMEM1>>>(x, N_NODES, dB1hi, dB1lo, dH1);
    k_agg1<<<aggBlk, TB>>>(b1);

    // layer 2: H2 = h @ W2 (HMMA) ; out = log_softmax(agg(H2) + b2)
    k_mma_gemm<128, 64, 40, 40><<<gemmBlk, 256, SMEM2>>>(dh, N_NODES, dB2hi, dB2lo, dH2);
    k_agg2<<<aggBlk, TB>>>(b2, out);
}

// round 4
// speedup vs baseline: 1.3618x; 1.0437x over previous
#include <cuda_runtime.h>
#include <cuda_bf16.h>
#include <math.h>
#include <stdint.h>

#define N_NODES 100000
#define N_EDGES 1600000
#define F_IN    256
#define F_HID   128
#define F_OUT   40
#define NSCAN_BLK 98            // ceil(100000/1024)

// ---------------- device scratch (static globals: allowed) ----------------
__device__ int   g_is64;
__device__ int   g_deg[N_NODES];
__device__ float g_dinv[N_NODES];
__device__ int   g_rowptr[N_NODES + 1];
__device__ int   g_cursor[N_NODES];
__device__ int   g_src[N_EDGES];
__device__ int   g_dst[N_EDGES];
__device__ int   g_ssrc[N_EDGES];       // src ids sorted by dst
__device__ int   g_bsum[NSCAN_BLK];
__device__ float g_H1[(size_t)N_NODES * F_HID];   // x @ W1
__device__ float g_h [(size_t)N_NODES * F_HID];   // relu(agg1 + b1)
__device__ float g_H2[(size_t)N_NODES * F_OUT];   // h @ W2
// W^T baked as N-major bf16 hi/lo: [N][K]
__device__ __align__(16) __nv_bfloat16 g_B1hi[128 * 256];
__device__ __align__(16) __nv_bfloat16 g_B1lo[128 * 256];
__device__ __align__(16) __nv_bfloat16 g_B2hi[64 * 128];
__device__ __align__(16) __nv_bfloat16 g_B2lo[64 * 128];

// ======================= mma.sync helpers (sm_80+ baseline PTX) ============
__device__ __forceinline__ uint32_t smem_u32(const void* p) {
    uint32_t a;
    asm("{ .reg .u64 t; cvta.to.shared.u64 t, %1; cvt.u32.u64 %0, t; }"
        : "=r"(a) : "l"(p));
    return a;
}

__device__ __forceinline__ void ldsm_x4(uint32_t* r, uint32_t addr) {
    asm volatile("ldmatrix.sync.aligned.m8n8.x4.shared.b16 {%0,%1,%2,%3}, [%4];"
                 : "=r"(r[0]), "=r"(r[1]), "=r"(r[2]), "=r"(r[3]) : "r"(addr));
}

__device__ __forceinline__ void mma_bf16(float* c, const uint32_t* a, const uint32_t* b) {
    asm volatile(
        "mma.sync.aligned.m16n8k16.row.col.f32.bf16.bf16.f32 "
        "{%0,%1,%2,%3}, {%4,%5,%6,%7}, {%8,%9}, {%0,%1,%2,%3};"
        : "+f"(c[0]), "+f"(c[1]), "+f"(c[2]), "+f"(c[3])
        : "r"(a[0]), "r"(a[1]), "r"(a[2]), "r"(a[3]), "r"(b[0]), "r"(b[1]));
}

// =================== tensor-core GEMM via mma.sync, bf16 split =============
template <int KDIM, int NDIM, int LDC, int NOUT>
__global__ __launch_bounds__(256, 1) void k_mma_gemm(
    const float* __restrict__ A, int M,
    const __nv_bfloat16* __restrict__ Bhi,
    const __nv_bfloat16* __restrict__ Blo,
    float* __restrict__ C)
{
    constexpr int PAD = 72;                 // bf16 per smem row (144 B)
    constexpr int NJT = (NDIM / 2) / 8;     // 8x8-col mma tiles per warp
    constexpr int A_HI = 0;
    constexpr int A_LO = 128 * PAD;
    constexpr int B_HI = 2 * 128 * PAD;
    constexpr int B_LO = B_HI + NDIM * PAD;

    extern __shared__ __nv_bfloat16 sm[];
    const uint32_t sb = smem_u32(sm);

    const int tid  = threadIdx.x;
    const int wid  = tid >> 5;
    const int lane = tid & 31;
    const int wm = wid & 3;
    const int wn = wid >> 2;
    const int m_warp = wm * 32;
    const int n_warp = wn * (NDIM / 2);
    const int m0 = blockIdx.x * 128;

    float acc[2][NJT][4];
#pragma unroll
    for (int i = 0; i < 2; i++)
#pragma unroll
        for (int j = 0; j < NJT; j++)
#pragma unroll
            for (int q = 0; q < 4; q++) acc[i][j][q] = 0.f;

    const int a_off = (m_warp + (lane & 15)) * PAD + ((lane >> 4) << 3);
    const int b_off = (n_warp + (lane & 7) + ((lane >> 4) << 3)) * PAD
                    + (((lane >> 3) & 1) << 3);

    for (int k0 = 0; k0 < KDIM; k0 += 64) {
        __syncthreads();
        // ---- fill A tile: 128 x 64 fp32 -> bf16 hi/lo ----
        {
            const int iters = 128 * 16 / 256;   // 8
#pragma unroll
            for (int t = 0; t < iters; t++) {
                int i = tid + t * 256;
                int m = i >> 4, q = i & 15;
                int rowg = m0 + m; if (rowg >= M) rowg = M - 1;
                float4 v = *(const float4*)(A + (size_t)rowg * KDIM + k0 + q * 4);
                __nv_bfloat16 h[4], l[4];
                float vv[4] = {v.x, v.y, v.z, v.w};
#pragma unroll
                for (int e = 0; e < 4; e++) {
                    h[e] = __float2bfloat16(vv[e]);
                    l[e] = __float2bfloat16(vv[e] - __bfloat162float(h[e]));
                }
                uint32_t hp0 = ((uint32_t)__bfloat16_as_ushort(h[1]) << 16) | __bfloat16_as_ushort(h[0]);
                uint32_t hp1 = ((uint32_t)__bfloat16_as_ushort(h[3]) << 16) | __bfloat16_as_ushort(h[2]);
                uint32_t lp0 = ((uint32_t)__bfloat16_as_ushort(l[1]) << 16) | __bfloat16_as_ushort(l[0]);
                uint32_t lp1 = ((uint32_t)__bfloat16_as_ushort(l[3]) << 16) | __bfloat16_as_ushort(l[2]);
                *(uint2*)(sm + A_HI + m * PAD + q * 4) = make_uint2(hp0, hp1);
                *(uint2*)(sm + A_LO + m * PAD + q * 4) = make_uint2(lp0, lp1);
            }
        }
        // ---- fill B tile: NDIM x 64 bf16 hi+lo (prebaked, linear copy) ----
        {
            const int per_img = NDIM * 8;       // uint4 per image
            const int iters = 2 * per_img / 256;
#pragma unroll
            for (int t = 0; t < iters; t++) {
                int i = tid + t * 256;
                int img = i >= per_img;
                int ii = i - img * per_img;
                int r = ii >> 3, q = ii & 7;
                const __nv_bfloat16* src = img ? Blo : Bhi;
                uint4 v = *(const uint4*)(src + (size_t)r * KDIM + k0 + q * 8);
                *(uint4*)(sm + (img ? B_LO : B_HI) + r * PAD + q * 8) = v;
            }
        }
        __syncthreads();

#pragma unroll
        for (int kk = 0; kk < 64; kk += 16) {
            uint32_t ah[2][4], al[2][4];
#pragma unroll
            for (int i = 0; i < 2; i++) {
                uint32_t base = (uint32_t)((a_off + i * 16 * PAD + kk) * 2);
                ldsm_x4(ah[i], sb + A_HI * 2 + base);
                ldsm_x4(al[i], sb + A_LO * 2 + base);
            }
            uint32_t bh[NJT][2], bl[NJT][2];
#pragma unroll
            for (int jj = 0; jj < NJT / 2; jj++) {
                uint32_t base = (uint32_t)((b_off + jj * 16 * PAD + kk) * 2);
                uint32_t r[4];
                ldsm_x4(r, sb + B_HI * 2 + base);
                bh[2*jj][0] = r[0]; bh[2*jj][1] = r[1];
                bh[2*jj+1][0] = r[2]; bh[2*jj+1][1] = r[3];
                ldsm_x4(r, sb + B_LO * 2 + base);
                bl[2*jj][0] = r[0]; bl[2*jj][1] = r[1];
                bl[2*jj+1][0] = r[2]; bl[2*jj+1][1] = r[3];
            }
#pragma unroll
            for (int i = 0; i < 2; i++)
#pragma unroll
                for (int j = 0; j < NJT; j++) {
                    mma_bf16(acc[i][j], ah[i], bh[j]);
                    mma_bf16(acc[i][j], ah[i], bl[j]);
                    mma_bf16(acc[i][j], al[i], bh[j]);
                }
        }
    }

#pragma unroll
    for (int i = 0; i < 2; i++) {
        int r0 = m0 + m_warp + i * 16 + (lane >> 2);
#pragma unroll
        for (int j = 0; j < NJT; j++) {
            int col = n_warp + j * 8 + (lane & 3) * 2;
            if (col < NOUT) {
                if (r0 < M) {
                    C[(size_t)r0 * LDC + col]     = acc[i][j][0];
                    C[(size_t)r0 * LDC + col + 1] = acc[i][j][1];
                }
                if (r0 + 8 < M) {
                    C[(size_t)(r0 + 8) * LDC + col]     = acc[i][j][2];
                    C[(size_t)(r0 + 8) * LDC + col + 1] = acc[i][j][3];
                }
            }
        }
    }
}

// bake W^T (N-major) hi/lo bf16
__global__ void k_prep_b(const float* __restrict__ W, int K, int N, int nact,
                         __nv_bfloat16* __restrict__ hi,
                         __nv_bfloat16* __restrict__ lo) {
    int idx = blockIdx.x * blockDim.x + threadIdx.x;
    if (idx >= N * K) return;
    int n = idx / K, k = idx % K;
    float v = (n < nact) ? W[(size_t)k * nact + n] : 0.f;
    __nv_bfloat16 h = __float2bfloat16(v);
    hi[idx] = h;
    lo[idx] = __float2bfloat16(v - __bfloat162float(h));
}

// ---------------- dtype detection -----------------------------------------
__global__ void k_detect(const unsigned* __restrict__ w) {
    __shared__ int any;
    if (threadIdx.x == 0) any = 0;
    __syncthreads();
    for (int j = threadIdx.x; j < 512; j += blockDim.x)
        if (w[2 * j + 1] != 0u) atomicOr(&any, 1);
    __syncthreads();
    if (threadIdx.x == 0) g_is64 = (any == 0);
}

__global__ void k_init_deg() {
    int i = blockIdx.x * blockDim.x + threadIdx.x;
    if (i < N_NODES) g_deg[i] = 1;   // self loop
}

__global__ void k_convert(const void* __restrict__ ei) {
    int e = blockIdx.x * blockDim.x + threadIdx.x;
    if (e >= N_EDGES) return;
    int s, d;
    if (g_is64) {
        const long long* p = (const long long*)ei;
        s = (int)p[e];
        d = (int)p[N_EDGES + e];
    } else {
        const int* p = (const int*)ei;
        s = p[e];
        d = p[N_EDGES + e];
    }
    g_src[e] = s;
    g_dst[e] = d;
    atomicAdd(&g_deg[d], 1);
}

__global__ void k_dinv() {
    int i = blockIdx.x * blockDim.x + threadIdx.x;
    if (i < N_NODES) g_dinv[i] = rsqrtf((float)g_deg[i]);
}

// ---------------- CSR build: 2-level exclusive scan of (deg-1) -------------
__global__ void k_scan1() {
    __shared__ int sh[1024];
    int tid = threadIdx.x;
    int i = blockIdx.x * 1024 + tid;
    int v = (i < N_NODES) ? (g_deg[i] - 1) : 0;
    sh[tid] = v;
    __syncthreads();
    for (int off = 1; off < 1024; off <<= 1) {
        int t = (tid >= off) ? sh[tid - off] : 0;
        __syncthreads();
        sh[tid] += t;
        __syncthreads();
    }
    if (i < N_NODES) g_rowptr[i] = sh[tid] - v;   // exclusive
    if (tid == 1023) g_bsum[blockIdx.x] = sh[1023];
}

__global__ void k_scan2() {
    __shared__ int sh[128];
    int tid = threadIdx.x;
    int v = (tid < NSCAN_BLK) ? g_bsum[tid] : 0;
    sh[tid] = v;
    __syncthreads();
    for (int off = 1; off < 128; off <<= 1) {
        int t = (tid >= off) ? sh[tid - off] : 0;
        __syncthreads();
        sh[tid] += t;
        __syncthreads();
    }
    if (tid < NSCAN_BLK) g_bsum[tid] = sh[tid] - v;
}

__global__ void k_scan3() {
    int i = blockIdx.x * blockDim.x + threadIdx.x;
    if (i < N_NODES) {
        int r = g_rowptr[i] + g_bsum[i >> 10];
        g_rowptr[i] = r;
        g_cursor[i] = r;
    } else if (i == N_NODES) {
        g_rowptr[N_NODES] = N_EDGES;
    }
}

__global__ void k_scatter() {
    int e = blockIdx.x * blockDim.x + threadIdx.x;
    if (e >= N_EDGES) return;
    int d = g_dst[e];
    int p = atomicAdd(&g_cursor[d], 1);
    g_ssrc[p] = g_src[e];
}

// ---------------- layer-1 aggregation: warp per node, MLP=4 unrolled ------
__global__ __launch_bounds__(256) void k_agg1(const float* __restrict__ b1) {
    int node = (blockIdx.x * blockDim.x + threadIdx.x) >> 5;
    if (node >= N_NODES) return;
    int lane = threadIdx.x & 31;
    float di = g_dinv[node];
    float wself = di * di;

    float4 v = ((const float4*)(g_H1 + (size_t)node * F_HID))[lane];
    float4 acc;
    acc.x = wself * v.x; acc.y = wself * v.y;
    acc.z = wself * v.z; acc.w = wself * v.w;

    int beg = g_rowptr[node], end = g_rowptr[node + 1];
    for (int p0 = beg; p0 < end; p0 += 32) {
        int myp = p0 + lane;
        int s = (myp < end) ? g_ssrc[myp] : 0;
        float ws = (myp < end) ? g_dinv[s] * di : 0.f;
        int cnt = min(32, end - p0);
        int j = 0;
        for (; j + 4 <= cnt; j += 4) {
            int   s0 = __shfl_sync(0xffffffffu, s, j);
            int   s1 = __shfl_sync(0xffffffffu, s, j + 1);
            int   s2 = __shfl_sync(0xffffffffu, s, j + 2);
            int   s3 = __shfl_sync(0xffffffffu, s, j + 3);
            float w0 = __shfl_sync(0xffffffffu, ws, j);
            float w1 = __shfl_sync(0xffffffffu, ws, j + 1);
            float w2 = __shfl_sync(0xffffffffu, ws, j + 2);
            float w3 = __shfl_sync(0xffffffffu, ws, j + 3);
            float4 u0 = ((const float4*)(g_H1 + (size_t)s0 * F_HID))[lane];
            float4 u1 = ((const float4*)(g_H1 + (size_t)s1 * F_HID))[lane];
            float4 u2 = ((const float4*)(g_H1 + (size_t)s2 * F_HID))[lane];
            float4 u3 = ((const float4*)(g_H1 + (size_t)s3 * F_HID))[lane];
            acc.x += w0 * u0.x; acc.y += w0 * u0.y; acc.z += w0 * u0.z; acc.w += w0 * u0.w;
            acc.x += w1 * u1.x; acc.y += w1 * u1.y; acc.z += w1 * u1.z; acc.w += w1 * u1.w;
            acc.x += w2 * u2.x; acc.y += w2 * u2.y; acc.z += w2 * u2.z; acc.w += w2 * u2.w;
            acc.x += w3 * u3.x; acc.y += w3 * u3.y; acc.z += w3 * u3.z; acc.w += w3 * u3.w;
        }
        for (; j < cnt; ++j) {
            int   sj = __shfl_sync(0xffffffffu, s, j);
            float wj = __shfl_sync(0xffffffffu, ws, j);
            float4 u = ((const float4*)(g_H1 + (size_t)sj * F_HID))[lane];
            acc.x += wj * u.x; acc.y += wj * u.y;
            acc.z += wj * u.z; acc.w += wj * u.w;
        }
    }
    float4 bb = ((const float4*)b1)[lane];
    acc.x = fmaxf(acc.x + bb.x, 0.f);
    acc.y = fmaxf(acc.y + bb.y, 0.f);
    acc.z = fmaxf(acc.z + bb.z, 0.f);
    acc.w = fmaxf(acc.w + bb.w, 0.f);
    ((float4*)(g_h + (size_t)node * F_HID))[lane] = acc;
}

// ---------- layer-2 aggregation + bias + log_softmax, MLP=4 unrolled ------
__global__ __launch_bounds__(256) void k_agg2(const float* __restrict__ b2,
                                              float* __restrict__ out) {
    int node = (blockIdx.x * blockDim.x + threadIdx.x) >> 5;
    if (node >= N_NODES) return;
    int lane = threadIdx.x & 31;
    float di = g_dinv[node];
    float wself = di * di;

    const float* srow = g_H2 + (size_t)node * F_OUT;
    float acc0 = wself * srow[lane];
    float acc1 = (lane < 8) ? wself * srow[32 + lane] : 0.f;

    int beg = g_rowptr[node], end = g_rowptr[node + 1];
    for (int p0 = beg; p0 < end; p0 += 32) {
        int myp = p0 + lane;
        int s = (myp < end) ? g_ssrc[myp] : 0;
        float ws = (myp < end) ? g_dinv[s] * di : 0.f;
        int cnt = min(32, end - p0);
        int j = 0;
        for (; j + 4 <= cnt; j += 4) {
            int   s0 = __shfl_sync(0xffffffffu, s, j);
            int   s1 = __shfl_sync(0xffffffffu, s, j + 1);
            int   s2 = __shfl_sync(0xffffffffu, s, j + 2);
            int   s3 = __shfl_sync(0xffffffffu, s, j + 3);
            float w0 = __shfl_sync(0xffffffffu, ws, j);
            float w1 = __shfl_sync(0xffffffffu, ws, j + 1);
            float w2 = __shfl_sync(0xffffffffu, ws, j + 2);
            float w3 = __shfl_sync(0xffffffffu, ws, j + 3);
            const float* r0 = g_H2 + (size_t)s0 * F_OUT;
            const float* r1 = g_H2 + (size_t)s1 * F_OUT;
            const float* r2 = g_H2 + (size_t)s2 * F_OUT;
            const float* r3 = g_H2 + (size_t)s3 * F_OUT;
            float a0 = r0[lane], a1 = r1[lane], a2 = r2[lane], a3 = r3[lane];
            acc0 += w0 * a0 + w1 * a1;
            acc0 += w2 * a2 + w3 * a3;
            if (lane < 8) {
                acc1 += w0 * r0[32 + lane] + w1 * r1[32 + lane];
                acc1 += w2 * r2[32 + lane] + w3 * r3[32 + lane];
            }
        }
        for (; j < cnt; ++j) {
            int   sj = __shfl_sync(0xffffffffu, s, j);
            float wj = __shfl_sync(0xffffffffu, ws, j);
            const float* r = g_H2 + (size_t)sj * F_OUT;
            acc0 += wj * r[lane];
            if (lane < 8) acc1 += wj * r[32 + lane];
        }
    }
    acc0 += b2[lane];
    if (lane < 8) acc1 += b2[32 + lane];

    float m = acc0;
    if (lane < 8) m = fmaxf(m, acc1);
#pragma unroll
    for (int o = 16; o; o >>= 1) m = fmaxf(m, __shfl_xor_sync(0xffffffffu, m, o));
    float e = expf(acc0 - m) + ((lane < 8) ? expf(acc1 - m) : 0.f);
#pragma unroll
    for (int o = 16; o; o >>= 1) e += __shfl_xor_sync(0xffffffffu, e, o);
    float lse = m + logf(e);

    float* orow = out + (size_t)node * F_OUT;
    orow[lane] = acc0 - lse;
    if (lane < 8) orow[32 + lane] = acc1 - lse;
}

// ---------------- host launcher --------------------------------------------
extern "C" void kernel_launch(void* const* d_in, const int* in_sizes, int n_in,
                              void* d_out, int out_size) {
    const float* x  = (const float*)d_in[0];
    const void*  ei = d_in[1];
    const float* W1 = (const float*)d_in[2];
    const float* b1 = (const float*)d_in[3];
    const float* W2 = (const float*)d_in[4];
    const float* b2 = (const float*)d_in[5];
    float* out = (float*)d_out;

    float *dH1, *dh, *dH2;
    __nv_bfloat16 *dB1hi, *dB1lo, *dB2hi, *dB2lo;
    cudaGetSymbolAddress((void**)&dH1,   g_H1);
    cudaGetSymbolAddress((void**)&dh,    g_h);
    cudaGetSymbolAddress((void**)&dH2,   g_H2);
    cudaGetSymbolAddress((void**)&dB1hi, g_B1hi);
    cudaGetSymbolAddress((void**)&dB1lo, g_B1lo);
    cudaGetSymbolAddress((void**)&dB2hi, g_B2hi);
    cudaGetSymbolAddress((void**)&dB2lo, g_B2lo);

    const int SMEM1 = (2 * 128 + 2 * 128) * 72 * 2;   // 73728
    const int SMEM2 = (2 * 128 + 2 * 64) * 72 * 2;    // 55296

    static cudaStream_t s2;
    static cudaEvent_t evFork, evJoin;
    static bool init_done = false;
    if (!init_done) {
        cudaFuncSetAttribute(k_mma_gemm<256, 128, 128, 128>,
                             cudaFuncAttributeMaxDynamicSharedMemorySize, SMEM1);
        cudaFuncSetAttribute(k_mma_gemm<128, 64, 40, 40>,
                             cudaFuncAttributeMaxDynamicSharedMemorySize, SMEM2);
        cudaStreamCreateWithFlags(&s2, cudaStreamNonBlocking);
        cudaEventCreateWithFlags(&evFork, cudaEventDisableTiming);
        cudaEventCreateWithFlags(&evJoin, cudaEventDisableTiming);
        init_done = true;
    }

    const int TB = 256;
    int nblkN = (N_NODES + TB - 1) / TB;
    int nblkE = (N_EDGES + TB - 1) / TB;
    int aggBlk = (N_NODES * 32) / TB;
    int gemmBlk = (N_NODES + 127) / 128;          // 782

    // ---- fork: side stream does weight bake + GEMM1 while main stream
    //      builds the CSR graph structure ----
    cudaEventRecord(evFork, 0);
    cudaStreamWaitEvent(s2, evFork, 0);

    // side stream: prep weights + GEMM1 (depends only on x, W1, W2)
    k_prep_b<<<(128 * 256 + TB - 1) / TB, TB, 0, s2>>>(W1, 256, 128, 128, dB1hi, dB1lo);
    k_prep_b<<<(64 * 128 + TB - 1) / TB, TB, 0, s2>>>(W2, 128, 64, 40, dB2hi, dB2lo);
    k_mma_gemm<256, 128, 128, 128><<<gemmBlk, 256, SMEM1, s2>>>(x, N_NODES, dB1hi, dB1lo, dH1);

    // main stream: graph preprocessing (depends only on edge_index)
    k_detect<<<1, 256>>>((const unsigned*)ei);
    k_init_deg<<<nblkN, TB>>>();
    k_convert<<<nblkE, TB>>>(ei);
    k_dinv<<<nblkN, TB>>>();
    k_scan1<<<NSCAN_BLK, 1024>>>();
    k_scan2<<<1, 128>>>();
    k_scan3<<<(N_NODES + 1 + TB - 1) / TB, TB>>>();
    k_scatter<<<nblkE, TB>>>();

    // ---- join ----
    cudaEventRecord(evJoin, s2);
    cudaStreamWaitEvent(0, evJoin, 0);

    // layer 1 aggregation, layer 2 GEMM, layer 2 aggregation + log_softmax
    k_agg1<<<aggBlk, TB>>>(b1);
    k_mma_gemm<128, 64, 40, 40><<<gemmBlk, 256, SMEM2>>>(dh, N_NODES, dB2hi, dB2lo, dH2);
    k_agg2<<<aggBlk, TB>>>(b2, out);
}